// round 6
// baseline (speedup 1.0000x reference)
#include <cuda_runtime.h>
#include <cuda_fp16.h>
#include <math.h>
#include <stdint.h>

#define NN 100000   // nodes
#define NR 4        // relations
#define NE 250000   // edges per relation
#define DD 128      // feature dim
#define NSEG (NR * NN)                 // 400000 segments
#define NBLK ((NSEG + 1023) / 1024)    // 391 scan blocks

// ---------------------------------------------------------------------------
// Scratch (__device__ globals; allocation-free rule)
// ---------------------------------------------------------------------------
__device__ __align__(16) __half g_xh[(size_t)NN * DD];         // fp16 x, 25.6MB
__device__ __align__(16) uint32_t g_wtfh[5 * 8 * 16 * 32 * 2]; // f16 fragment-packed W
__device__ int g_cnt[NSEG];
__device__ int g_off[NSEG];
__device__ int g_cur[NSEG];
__device__ int g_ssrc[NR * NE];    // src ids sorted by (rel,dst)
__device__ int g_sdst[NR * NE];    // dst ids sorted by (rel,dst)
__device__ int g_bsum[512];

// m16n8k16 F16 mma.sync (family-common PTX), fp32 accumulate
__device__ __forceinline__ void mma16(float* d, const uint32_t* a,
                                      uint32_t b0, uint32_t b1) {
    asm volatile(
        "mma.sync.aligned.m16n8k16.row.col.f32.f16.f16.f32 "
        "{%0,%1,%2,%3}, {%4,%5,%6,%7}, {%8,%9}, {%0,%1,%2,%3};"
        : "+f"(d[0]), "+f"(d[1]), "+f"(d[2]), "+f"(d[3])
        : "r"(a[0]), "r"(a[1]), "r"(a[2]), "r"(a[3]), "r"(b0), "r"(b1));
}

// ---------------------------------------------------------------------------
// CSR build
// ---------------------------------------------------------------------------
__global__ void zero_cnt_kernel() {
    int i = blockIdx.x * blockDim.x + threadIdx.x;
    if (i < NSEG) g_cnt[i] = 0;
    if (i < 512) g_bsum[i] = 0;
}
__global__ void hist_kernel(const int* __restrict__ dst) {
    int e = blockIdx.x * blockDim.x + threadIdx.x;
    if (e >= NR * NE) return;
    atomicAdd(&g_cnt[(e / NE) * NN + dst[e]], 1);
}
__global__ void scan1_kernel() {
    __shared__ int sh[1024];
    int gi = blockIdx.x * 1024 + threadIdx.x;
    int v = (gi < NSEG) ? g_cnt[gi] : 0;
    sh[threadIdx.x] = v;
    __syncthreads();
#pragma unroll
    for (int o = 1; o < 1024; o <<= 1) {
        int t = (threadIdx.x >= o) ? sh[threadIdx.x - o] : 0;
        __syncthreads();
        sh[threadIdx.x] += t;
        __syncthreads();
    }
    if (gi < NSEG) g_off[gi] = sh[threadIdx.x] - v;
    if (threadIdx.x == 1023) g_bsum[blockIdx.x] = sh[1023];
}
__global__ void scan2_kernel() {
    __shared__ int sh[512];
    int v = (threadIdx.x < NBLK) ? g_bsum[threadIdx.x] : 0;
    sh[threadIdx.x] = v;
    __syncthreads();
#pragma unroll
    for (int o = 1; o < 512; o <<= 1) {
        int t = (threadIdx.x >= o) ? sh[threadIdx.x - o] : 0;
        __syncthreads();
        sh[threadIdx.x] += t;
        __syncthreads();
    }
    if (threadIdx.x < NBLK) g_bsum[threadIdx.x] = sh[threadIdx.x] - v;
}
__global__ void scan3_kernel() {
    int gi = blockIdx.x * 1024 + threadIdx.x;
    if (gi < NSEG) {
        int o = g_off[gi] + g_bsum[blockIdx.x];
        g_off[gi] = o;
        g_cur[gi] = o;
    }
}
__global__ void place_kernel(const int* __restrict__ src,
                             const int* __restrict__ dst) {
    int e = blockIdx.x * blockDim.x + threadIdx.x;
    if (e >= NR * NE) return;
    int d = dst[e];
    int pos = atomicAdd(&g_cur[(e / NE) * NN + d], 1);
    g_ssrc[pos] = src[e];
    g_sdst[pos] = d;
}

// ---------------------------------------------------------------------------
// x -> fp16 (read once)
// ---------------------------------------------------------------------------
__global__ void xh_kernel(const float* __restrict__ x) {
    int idx = blockIdx.x * blockDim.x + threadIdx.x;   // one float4 each
    if (idx >= NN * DD / 4) return;
    float4 v = reinterpret_cast<const float4*>(x)[idx];
    union { __half2 h[2]; uint2 u; } p;
    p.h[0] = __floats2half2_rn(v.x, v.y);
    p.h[1] = __floats2half2_rn(v.z, v.w);
    reinterpret_cast<uint2*>(g_xh)[idx] = p.u;
}

// ---------------------------------------------------------------------------
// Weight prep: pack f16(W[k][n]) in m16n8k16 B-fragment order.
// ---------------------------------------------------------------------------
__global__ void wt_kernel(const float* __restrict__ weight,
                          const float* __restrict__ loop_weight) {
    int idx = blockIdx.x * blockDim.x + threadIdx.x;   // 0 .. 40959
    if (idx >= 5 * 8 * 16 * 32 * 2) return;
    int r = idx & 1;
    int l = (idx >> 1) & 31;
    int j = (idx >> 6) & 15;
    int t = (idx >> 10) & 7;
    int s = idx >> 13;
    int n = j * 8 + (l >> 2);
    int k = t * 16 + 2 * (l & 3) + 8 * r;
    const float* W = (s < 4) ? weight + (size_t)s * DD * DD : loop_weight;
    union { __half2 h; uint32_t u; } p;
    p.h = __floats2half2_rn(W[(size_t)k * DD + n], W[(size_t)(k + 1) * DD + n]);
    g_wtfh[idx] = p.u;
}

// ---------------------------------------------------------------------------
// Fused gather + F16 mma.sync 5-way GEMM + epilogue.
// Block 256 = 4 M-warps x 2 N-warps; tile M=128, N=128, K=128/stage.
// Stages 0..3 gather their A tile edge-parallel from g_xh via CSR slice.
// SMEM: bias | Aacc fp32 (feature-permuted) | As f16 | W frags.
// ---------------------------------------------------------------------------
#define LDAH 136                                   // padded A row (halves)
#define LACC 132                                   // padded Aacc row (floats)
#define OFF_BIAS 0
#define OFF_AACC 2560
#define OFF_AS   (OFF_AACC + 128 * LACC * 4)       // 2560 + 67584 = 70144
#define OFF_W    (OFF_AS + 128 * LDAH * 2)         // 70144 + 34816 = 104960
#define SMEM_TOTAL (OFF_W + 32768)                 // 137728

__global__ __launch_bounds__(256)
void gemm_mma(const float* __restrict__ conv_bias,
              const float* __restrict__ node_bias,
              float* __restrict__ out) {
    extern __shared__ char smem[];
    float* sbias = reinterpret_cast<float*>(smem + OFF_BIAS);
    float* Aacc  = reinterpret_cast<float*>(smem + OFF_AACC);
    __half* As   = reinterpret_cast<__half*>(smem + OFF_AS);
    const uint2* Bw = reinterpret_cast<const uint2*>(smem + OFF_W);

    const int tid   = threadIdx.x;
    const int lane  = tid & 31;
    const int warp  = tid >> 5;
    const int mwarp = warp & 3;        // 0..3 (M)
    const int nwarp = warp >> 2;       // 0..1 (N)
    const int mbase = blockIdx.x * 128;
    const int lr    = lane >> 2;       // 0..7
    const int lc    = lane & 3;        // 0..3
    const int rows  = (NN - mbase < 128) ? (NN - mbase) : 128;

    for (int i = tid; i < 512; i += 256) sbias[i] = conv_bias[i];
    for (int i = tid; i < 128; i += 256) sbias[512 + i] = node_bias[i];

    float hsum[2][8][4];
#pragma unroll
    for (int mi = 0; mi < 2; mi++)
#pragma unroll
        for (int j = 0; j < 8; j++)
#pragma unroll
            for (int r = 0; r < 4; r++) hsum[mi][j][r] = 0.f;

    float acc[2][8][4];
    const uint2* xh2 = reinterpret_cast<const uint2*>(g_xh);

    for (int s = 0; s < 5; s++) {
        __syncthreads();   // previous stage's As/W reads complete
        // --- stage fragment-packed W (32 KB, L2-hot) ---
        const uint4* Wg = reinterpret_cast<const uint4*>(g_wtfh) + (size_t)s * 2048;
#pragma unroll
        for (int it = 0; it < 8; it++)
            *reinterpret_cast<uint4*>(smem + OFF_W + (tid + it * 256) * 16) =
                Wg[tid + it * 256];

        if (s < 4) {
            // --- zero Aacc (128 x LACC fp32) ---
            uint4 z = make_uint4(0u, 0u, 0u, 0u);
#pragma unroll
            for (int it = 0; it < 17; it++) {
                int idx = tid + it * 256;
                if (idx < 128 * LACC / 4)
                    reinterpret_cast<uint4*>(Aacc)[idx] = z;
            }
            __syncthreads();

            // --- edge-parallel gather: this block's CSR slice is contiguous ---
            const int seg0 = s * NN + mbase;
            const int eb = g_off[seg0];
            const int segh = seg0 + rows;
            const int ee = (segh < NSEG) ? g_off[segh] : NR * NE;
            for (int e = eb + warp; e < ee; e += 8) {
                int srcn = g_ssrc[e];                 // uniform within warp
                int row  = g_sdst[e] - mbase;
                uint2 v = xh2[(size_t)srcn * 32 + lane];
                float2 f01 = __half22float2(*reinterpret_cast<__half2*>(&v.x));
                float2 f23 = __half22float2(*reinterpret_cast<__half2*>(&v.y));
                float* ar = Aacc + row * LACC + lane; // slot i*32+lane = feature 4*lane+i
                atomicAdd(ar,      f01.x);
                atomicAdd(ar + 32, f01.y);
                atomicAdd(ar + 64, f23.x);
                atomicAdd(ar + 96, f23.y);
            }
            __syncthreads();

            // --- normalize + convert to f16 A tile ---
#pragma unroll
            for (int it = 0; it < 16; it++) {
                int lin = tid + it * 256;             // 0..4095
                int r = lin >> 5, c4 = lin & 31;
                int gr = mbase + r;
                union { __half2 h[2]; uint2 u; } p;
                if (gr < NN) {
                    int seg = s * NN + gr;
                    float rd = 1.0f / fmaxf((float)(g_cur[seg] - g_off[seg]), 1.0f);
                    const float* ar = Aacc + r * LACC + c4;
                    p.h[0] = __floats2half2_rn(ar[0] * rd,  ar[32] * rd);
                    p.h[1] = __floats2half2_rn(ar[64] * rd, ar[96] * rd);
                } else {
                    p.u = make_uint2(0u, 0u);
                }
                *reinterpret_cast<uint2*>(As + r * LDAH + c4 * 4) = p.u;
            }
        } else {
            // --- stage A tile directly from fp16 x ---
#pragma unroll
            for (int it = 0; it < 8; it++) {
                int lin = tid + it * 256;             // 0..2047
                int row = lin >> 4, c8 = lin & 15;
                int gr = mbase + row;
                uint4 v = make_uint4(0u, 0u, 0u, 0u);
                if (gr < NN)
                    v = reinterpret_cast<const uint4*>(g_xh)[(size_t)gr * 16 + c8];
                *reinterpret_cast<uint4*>(As + row * LDAH + c8 * 8) = v;
            }
        }
        __syncthreads();

#pragma unroll
        for (int mi = 0; mi < 2; mi++)
#pragma unroll
            for (int j = 0; j < 8; j++)
#pragma unroll
                for (int r = 0; r < 4; r++) acc[mi][j][r] = 0.f;

        // --- mainloop: 8 k-steps of K=16 ---
#pragma unroll
        for (int t = 0; t < 8; t++) {
            int c0 = t * 16 + 2 * lc;
            uint32_t a[2][4];
#pragma unroll
            for (int mi = 0; mi < 2; mi++) {
                int rr = mwarp * 32 + mi * 16 + lr;
                a[mi][0] = *reinterpret_cast<const uint32_t*>(As + rr * LDAH + c0);
                a[mi][1] = *reinterpret_cast<const uint32_t*>(As + (rr + 8) * LDAH + c0);
                a[mi][2] = *reinterpret_cast<const uint32_t*>(As + rr * LDAH + c0 + 8);
                a[mi][3] = *reinterpret_cast<const uint32_t*>(As + (rr + 8) * LDAH + c0 + 8);
            }
            uint2 b[8];
#pragma unroll
            for (int jj = 0; jj < 8; jj++)
                b[jj] = Bw[(t * 16 + nwarp * 8 + jj) * 32 + lane];
#pragma unroll
            for (int mi = 0; mi < 2; mi++)
#pragma unroll
                for (int jj = 0; jj < 8; jj++)
                    mma16(acc[mi][jj], a[mi], b[jj].x, b[jj].y);
        }

        if (s < 4) {
            // --- per-relation epilogue: relu(acc + bias) accumulated ---
#pragma unroll
            for (int mi = 0; mi < 2; mi++)
#pragma unroll
                for (int j = 0; j < 8; j++) {
                    int col = nwarp * 64 + j * 8 + lc * 2;
                    float b0 = sbias[s * 128 + col];
                    float b1 = sbias[s * 128 + col + 1];
                    hsum[mi][j][0] += fmaxf(acc[mi][j][0] + b0, 0.f);
                    hsum[mi][j][1] += fmaxf(acc[mi][j][1] + b1, 0.f);
                    hsum[mi][j][2] += fmaxf(acc[mi][j][2] + b0, 0.f);
                    hsum[mi][j][3] += fmaxf(acc[mi][j][3] + b1, 0.f);
                }
        } else {
            // --- final epilogue: mean, SiLU, + self-loop + node bias, ReLU ---
#pragma unroll
            for (int mi = 0; mi < 2; mi++) {
                int row = mbase + mwarp * 32 + mi * 16 + lr;
#pragma unroll
                for (int j = 0; j < 8; j++) {
                    int col = nwarp * 64 + j * 8 + lc * 2;
                    float nb0 = sbias[512 + col];
                    float nb1 = sbias[512 + col + 1];
                    float h, o0, o1;
                    if (row < NN) {
                        h = hsum[mi][j][0] * 0.25f;
                        h = h / (1.f + __expf(-h));
                        o0 = fmaxf(h + acc[mi][j][0] + nb0, 0.f);
                        h = hsum[mi][j][1] * 0.25f;
                        h = h / (1.f + __expf(-h));
                        o1 = fmaxf(h + acc[mi][j][1] + nb1, 0.f);
                        *reinterpret_cast<float2*>(out + (size_t)row * DD + col) =
                            make_float2(o0, o1);
                    }
                    if (row + 8 < NN) {
                        h = hsum[mi][j][2] * 0.25f;
                        h = h / (1.f + __expf(-h));
                        o0 = fmaxf(h + acc[mi][j][2] + nb0, 0.f);
                        h = hsum[mi][j][3] * 0.25f;
                        h = h / (1.f + __expf(-h));
                        o1 = fmaxf(h + acc[mi][j][3] + nb1, 0.f);
                        *reinterpret_cast<float2*>(out + (size_t)(row + 8) * DD + col) =
                            make_float2(o0, o1);
                    }
                }
            }
        }
    }
}

// ---------------------------------------------------------------------------
extern "C" void kernel_launch(void* const* d_in, const int* in_sizes, int n_in,
                              void* d_out, int out_size) {
    const float* x           = (const float*)d_in[0];
    const float* weight      = (const float*)d_in[1];
    const float* conv_bias   = (const float*)d_in[2];
    const float* loop_weight = (const float*)d_in[3];
    const float* node_bias   = (const float*)d_in[4];
    const int*   src         = (const int*)d_in[5];
    const int*   dst         = (const int*)d_in[6];
    float* out = (float*)d_out;

    // CSR build
    zero_cnt_kernel<<<(NSEG + 1023) / 1024, 1024>>>();
    hist_kernel<<<(NR * NE + 255) / 256, 256>>>(dst);
    scan1_kernel<<<NBLK, 1024>>>();
    scan2_kernel<<<1, 512>>>();
    scan3_kernel<<<NBLK, 1024>>>();
    place_kernel<<<(NR * NE + 255) / 256, 256>>>(src, dst);

    // x -> fp16, weight fragment pack
    xh_kernel<<<(NN * DD / 4 + 255) / 256, 256>>>(x);
    wt_kernel<<<(5 * 8 * 16 * 32 * 2 + 255) / 256, 256>>>(weight, loop_weight);

    // Fused gather + tensor-core GEMM + epilogue
    cudaFuncSetAttribute(gemm_mma, cudaFuncAttributeMaxDynamicSharedMemorySize,
                         SMEM_TOTAL);
    gemm_mma<<<(NN + 127) / 128, 256, SMEM_TOTAL>>>(conv_bias, node_bias, out);
}

// round 7
// speedup vs baseline: 3.0002x; 3.0002x over previous
#include <cuda_runtime.h>
#include <cuda_fp16.h>
#include <math.h>
#include <stdint.h>

#define NN 100000   // nodes
#define NR 4        // relations
#define NE 250000   // edges per relation
#define DD 128      // feature dim
#define NSEG (NR * NN)                 // 400000 segments
#define NBLK ((NSEG + 1023) / 1024)    // 391 scan blocks

// ---------------------------------------------------------------------------
// Scratch (__device__ globals; allocation-free rule)
// ---------------------------------------------------------------------------
__device__ __align__(16) __half g_xh[(size_t)NN * DD];         // fp16 x, 25.6MB
__device__ __align__(16) __half g_aggh[(size_t)NR * NN * DD];  // fp16 aggregate
__device__ __align__(16) uint32_t g_wtfh[5 * 8 * 8 * 32 * 4];  // f16 paired-frag W
__device__ int g_cnt[NSEG];
__device__ int g_off[NSEG];
__device__ int g_cur[NSEG];
__device__ int g_ssrc[NR * NE];
__device__ int g_bsum[512];

// m16n8k16 F16 mma.sync (family-common PTX), fp32 accumulate
__device__ __forceinline__ void mma16(float* d, const uint32_t* a,
                                      uint32_t b0, uint32_t b1) {
    asm volatile(
        "mma.sync.aligned.m16n8k16.row.col.f32.f16.f16.f32 "
        "{%0,%1,%2,%3}, {%4,%5,%6,%7}, {%8,%9}, {%0,%1,%2,%3};"
        : "+f"(d[0]), "+f"(d[1]), "+f"(d[2]), "+f"(d[3])
        : "r"(a[0]), "r"(a[1]), "r"(a[2]), "r"(a[3]), "r"(b0), "r"(b1));
}

// ---------------------------------------------------------------------------
// CSR build
// ---------------------------------------------------------------------------
__global__ void zero_cnt_kernel() {
    int i = blockIdx.x * blockDim.x + threadIdx.x;
    if (i < NSEG) g_cnt[i] = 0;
    if (i < 512) g_bsum[i] = 0;
}
__global__ void hist_kernel(const int* __restrict__ dst) {
    int e = blockIdx.x * blockDim.x + threadIdx.x;
    if (e >= NR * NE) return;
    atomicAdd(&g_cnt[(e / NE) * NN + dst[e]], 1);
}
__global__ void scan1_kernel() {
    __shared__ int sh[1024];
    int gi = blockIdx.x * 1024 + threadIdx.x;
    int v = (gi < NSEG) ? g_cnt[gi] : 0;
    sh[threadIdx.x] = v;
    __syncthreads();
#pragma unroll
    for (int o = 1; o < 1024; o <<= 1) {
        int t = (threadIdx.x >= o) ? sh[threadIdx.x - o] : 0;
        __syncthreads();
        sh[threadIdx.x] += t;
        __syncthreads();
    }
    if (gi < NSEG) g_off[gi] = sh[threadIdx.x] - v;
    if (threadIdx.x == 1023) g_bsum[blockIdx.x] = sh[1023];
}
__global__ void scan2_kernel() {
    __shared__ int sh[512];
    int v = (threadIdx.x < NBLK) ? g_bsum[threadIdx.x] : 0;
    sh[threadIdx.x] = v;
    __syncthreads();
#pragma unroll
    for (int o = 1; o < 512; o <<= 1) {
        int t = (threadIdx.x >= o) ? sh[threadIdx.x - o] : 0;
        __syncthreads();
        sh[threadIdx.x] += t;
        __syncthreads();
    }
    if (threadIdx.x < NBLK) g_bsum[threadIdx.x] = sh[threadIdx.x] - v;
}
__global__ void scan3_kernel() {
    int gi = blockIdx.x * 1024 + threadIdx.x;
    if (gi < NSEG) {
        int o = g_off[gi] + g_bsum[blockIdx.x];
        g_off[gi] = o;
        g_cur[gi] = o;
    }
}
__global__ void place_kernel(const int* __restrict__ src,
                             const int* __restrict__ dst) {
    int e = blockIdx.x * blockDim.x + threadIdx.x;
    if (e >= NR * NE) return;
    int pos = atomicAdd(&g_cur[(e / NE) * NN + dst[e]], 1);
    g_ssrc[pos] = src[e];
}

// ---------------------------------------------------------------------------
// x -> fp16 (read x fp32 exactly once)
// ---------------------------------------------------------------------------
__global__ void xh_kernel(const float* __restrict__ x) {
    int idx = blockIdx.x * blockDim.x + threadIdx.x;
    if (idx >= NN * DD / 4) return;
    float4 v = reinterpret_cast<const float4*>(x)[idx];
    union { __half2 h[2]; uint2 u; } p;
    p.h[0] = __floats2half2_rn(v.x, v.y);
    p.h[1] = __floats2half2_rn(v.z, v.w);
    reinterpret_cast<uint2*>(g_xh)[idx] = p.u;
}

// ---------------------------------------------------------------------------
// Gather: one warp per (rel,node); reads fp16 x, fp32 accumulate, fp16 store.
// ---------------------------------------------------------------------------
__global__ void gather_kernel() {
    unsigned wid  = (blockIdx.x * blockDim.x + threadIdx.x) >> 5;
    unsigned lane = threadIdx.x & 31;
    if (wid >= (unsigned)NSEG) return;
    int beg = g_off[wid];
    int end = g_cur[wid];
    const uint2* xh2 = reinterpret_cast<const uint2*>(g_xh);
    float a0 = 0.f, a1 = 0.f, a2 = 0.f, a3 = 0.f;
    float b0 = 0.f, b1 = 0.f, b2 = 0.f, b3 = 0.f;
    int e = beg;
    for (; e + 1 < end; e += 2) {
        int s0 = __ldg(&g_ssrc[e]);
        int s1 = __ldg(&g_ssrc[e + 1]);
        uint2 v0 = xh2[(size_t)s0 * 32 + lane];
        uint2 v1 = xh2[(size_t)s1 * 32 + lane];
        float2 p0 = __half22float2(*reinterpret_cast<__half2*>(&v0.x));
        float2 p1 = __half22float2(*reinterpret_cast<__half2*>(&v0.y));
        float2 q0 = __half22float2(*reinterpret_cast<__half2*>(&v1.x));
        float2 q1 = __half22float2(*reinterpret_cast<__half2*>(&v1.y));
        a0 += p0.x; a1 += p0.y; a2 += p1.x; a3 += p1.y;
        b0 += q0.x; b1 += q0.y; b2 += q1.x; b3 += q1.y;
    }
    if (e < end) {
        int s0 = __ldg(&g_ssrc[e]);
        uint2 v0 = xh2[(size_t)s0 * 32 + lane];
        float2 p0 = __half22float2(*reinterpret_cast<__half2*>(&v0.x));
        float2 p1 = __half22float2(*reinterpret_cast<__half2*>(&v0.y));
        a0 += p0.x; a1 += p0.y; a2 += p1.x; a3 += p1.y;
    }
    float rd = 1.0f / fmaxf((float)(end - beg), 1.0f);
    union { __half2 h[2]; uint2 u; } p;
    p.h[0] = __floats2half2_rn((a0 + b0) * rd, (a1 + b1) * rd);
    p.h[1] = __floats2half2_rn((a2 + b2) * rd, (a3 + b3) * rd);
    reinterpret_cast<uint2*>(g_aggh)[(size_t)wid * 32 + lane] = p.u;
}

// ---------------------------------------------------------------------------
// Weight prep: pack f16(W[k][n]) in PAIRED m16n8k16 B-fragment order.
// uint4 index: (((s*8 + t)*8 + q)*32 + l), components:
//   x = b0(j=2q), y = b1(j=2q), z = b0(j=2q+1), w = b1(j=2q+1)
//   n = j*8 + l/4 ;  k = t*16 + 2*(l%4) + 8*r  (half2 = {k, k+1})
// ---------------------------------------------------------------------------
__global__ void wt_kernel(const float* __restrict__ weight,
                          const float* __restrict__ loop_weight) {
    int idx = blockIdx.x * blockDim.x + threadIdx.x;   // 0 .. 40959 (uint32 slots)
    if (idx >= 5 * 8 * 8 * 32 * 4) return;
    int c = idx & 3;             // component in uint4
    int l = (idx >> 2) & 31;
    int q = (idx >> 7) & 7;
    int t = (idx >> 10) & 7;
    int s = idx >> 13;
    int j = 2 * q + (c >> 1);
    int r = c & 1;
    int n = j * 8 + (l >> 2);
    int k = t * 16 + 2 * (l & 3) + 8 * r;
    const float* W = (s < 4) ? weight + (size_t)s * DD * DD : loop_weight;
    union { __half2 h; uint32_t u; } p;
    p.h = __floats2half2_rn(W[(size_t)k * DD + n], W[(size_t)(k + 1) * DD + n]);
    g_wtfh[idx] = p.u;
}

// ---------------------------------------------------------------------------
// F16 mma.sync fused 5-way GEMM + epilogue.
// Block 256 = 4 M-warps x 2 N-warps; tile M=128, N=128, K=128/stage.
// ---------------------------------------------------------------------------
#define LDAH 136                                  // padded A row (halves)
#define OFF_BIAS 0
#define OFF_A    4096
#define OFF_W    (OFF_A + 128 * LDAH * 2)         // 4096 + 34816 = 38912
#define SMEM_TOTAL (OFF_W + 32768)                // 71680

__global__ __launch_bounds__(256)
void gemm_mma(const float* __restrict__ conv_bias,
              const float* __restrict__ node_bias,
              float* __restrict__ out) {
    extern __shared__ char smem[];
    float* sbias = reinterpret_cast<float*>(smem + OFF_BIAS);
    __half* As   = reinterpret_cast<__half*>(smem + OFF_A);
    const uint4* Bw = reinterpret_cast<const uint4*>(smem + OFF_W);

    const int tid   = threadIdx.x;
    const int lane  = tid & 31;
    const int warp  = tid >> 5;
    const int mwarp = warp & 3;        // 0..3 (M)
    const int nwarp = warp >> 2;       // 0..1 (N)
    const int mbase = blockIdx.x * 128;
    const int lr    = lane >> 2;       // 0..7
    const int lc    = lane & 3;        // 0..3

    for (int i = tid; i < 512; i += 256) sbias[i] = conv_bias[i];
    for (int i = tid; i < 128; i += 256) sbias[512 + i] = node_bias[i];

    float hsum[2][8][4];
#pragma unroll
    for (int mi = 0; mi < 2; mi++)
#pragma unroll
        for (int j = 0; j < 8; j++)
#pragma unroll
            for (int r = 0; r < 4; r++) hsum[mi][j][r] = 0.f;

    float acc[2][8][4];

    for (int s = 0; s < 5; s++) {
        __syncthreads();
        // --- stage A tile (128 x 128 f16) into padded SMEM ---
        const uint4* Ag = (s < 4)
            ? reinterpret_cast<const uint4*>(g_aggh) + (size_t)s * NN * 16
            : reinterpret_cast<const uint4*>(g_xh);
#pragma unroll
        for (int it = 0; it < 8; it++) {
            int lin = tid + it * 256;          // 0..2047
            int row = lin >> 4, c8 = lin & 15;
            int gr = mbase + row;
            uint4 v = make_uint4(0u, 0u, 0u, 0u);
            if (gr < NN) v = Ag[(size_t)gr * 16 + c8];
            *reinterpret_cast<uint4*>(As + row * LDAH + c8 * 8) = v;
        }
        // --- stage paired-fragment W (32 KB, L2-hot) ---
        const uint4* Wg = reinterpret_cast<const uint4*>(g_wtfh) + (size_t)s * 2048;
#pragma unroll
        for (int it = 0; it < 8; it++)
            *reinterpret_cast<uint4*>(smem + OFF_W + (tid + it * 256) * 16) =
                Wg[tid + it * 256];
        __syncthreads();

#pragma unroll
        for (int mi = 0; mi < 2; mi++)
#pragma unroll
            for (int j = 0; j < 8; j++)
#pragma unroll
                for (int r = 0; r < 4; r++) acc[mi][j][r] = 0.f;

        // --- mainloop: 8 k-steps of K=16 ---
#pragma unroll
        for (int t = 0; t < 8; t++) {
            int c0 = t * 16 + 2 * lc;
            uint32_t a[2][4];
#pragma unroll
            for (int mi = 0; mi < 2; mi++) {
                int rr = mwarp * 32 + mi * 16 + lr;
                a[mi][0] = *reinterpret_cast<const uint32_t*>(As + rr * LDAH + c0);
                a[mi][1] = *reinterpret_cast<const uint32_t*>(As + (rr + 8) * LDAH + c0);
                a[mi][2] = *reinterpret_cast<const uint32_t*>(As + rr * LDAH + c0 + 8);
                a[mi][3] = *reinterpret_cast<const uint32_t*>(As + (rr + 8) * LDAH + c0 + 8);
            }
            uint4 b[4];
#pragma unroll
            for (int p = 0; p < 4; p++)
                b[p] = Bw[(t * 8 + nwarp * 4 + p) * 32 + lane];
#pragma unroll
            for (int mi = 0; mi < 2; mi++)
#pragma unroll
                for (int p = 0; p < 4; p++) {
                    mma16(acc[mi][2 * p],     a[mi], b[p].x, b[p].y);
                    mma16(acc[mi][2 * p + 1], a[mi], b[p].z, b[p].w);
                }
        }

        if (s < 4) {
            // --- per-relation epilogue: relu(acc + bias) accumulated ---
#pragma unroll
            for (int mi = 0; mi < 2; mi++)
#pragma unroll
                for (int j = 0; j < 8; j++) {
                    int col = nwarp * 64 + j * 8 + lc * 2;
                    float b0 = sbias[s * 128 + col];
                    float b1 = sbias[s * 128 + col + 1];
                    hsum[mi][j][0] += fmaxf(acc[mi][j][0] + b0, 0.f);
                    hsum[mi][j][1] += fmaxf(acc[mi][j][1] + b1, 0.f);
                    hsum[mi][j][2] += fmaxf(acc[mi][j][2] + b0, 0.f);
                    hsum[mi][j][3] += fmaxf(acc[mi][j][3] + b1, 0.f);
                }
        } else {
            // --- final epilogue: mean, SiLU, + self-loop + node bias, ReLU ---
#pragma unroll
            for (int mi = 0; mi < 2; mi++) {
                int row = mbase + mwarp * 32 + mi * 16 + lr;
#pragma unroll
                for (int j = 0; j < 8; j++) {
                    int col = nwarp * 64 + j * 8 + lc * 2;
                    float nb0 = sbias[512 + col];
                    float nb1 = sbias[512 + col + 1];
                    float h, o0, o1;
                    if (row < NN) {
                        h = hsum[mi][j][0] * 0.25f;
                        h = h / (1.f + __expf(-h));
                        o0 = fmaxf(h + acc[mi][j][0] + nb0, 0.f);
                        h = hsum[mi][j][1] * 0.25f;
                        h = h / (1.f + __expf(-h));
                        o1 = fmaxf(h + acc[mi][j][1] + nb1, 0.f);
                        *reinterpret_cast<float2*>(out + (size_t)row * DD + col) =
                            make_float2(o0, o1);
                    }
                    if (row + 8 < NN) {
                        h = hsum[mi][j][2] * 0.25f;
                        h = h / (1.f + __expf(-h));
                        o0 = fmaxf(h + acc[mi][j][2] + nb0, 0.f);
                        h = hsum[mi][j][3] * 0.25f;
                        h = h / (1.f + __expf(-h));
                        o1 = fmaxf(h + acc[mi][j][3] + nb1, 0.f);
                        *reinterpret_cast<float2*>(out + (size_t)(row + 8) * DD + col) =
                            make_float2(o0, o1);
                    }
                }
            }
        }
    }
}

// ---------------------------------------------------------------------------
extern "C" void kernel_launch(void* const* d_in, const int* in_sizes, int n_in,
                              void* d_out, int out_size) {
    const float* x           = (const float*)d_in[0];
    const float* weight      = (const float*)d_in[1];
    const float* conv_bias   = (const float*)d_in[2];
    const float* loop_weight = (const float*)d_in[3];
    const float* node_bias   = (const float*)d_in[4];
    const int*   src         = (const int*)d_in[5];
    const int*   dst         = (const int*)d_in[6];
    float* out = (float*)d_out;

    // CSR build
    zero_cnt_kernel<<<(NSEG + 1023) / 1024, 1024>>>();
    hist_kernel<<<(NR * NE + 255) / 256, 256>>>(dst);
    scan1_kernel<<<NBLK, 1024>>>();
    scan2_kernel<<<1, 512>>>();
    scan3_kernel<<<NBLK, 1024>>>();
    place_kernel<<<(NR * NE + 255) / 256, 256>>>(src, dst);

    // x -> fp16, weight fragment pack
    xh_kernel<<<(NN * DD / 4 + 255) / 256, 256>>>(x);
    wt_kernel<<<(5 * 8 * 8 * 32 * 4 + 255) / 256, 256>>>(weight, loop_weight);

    // Gather (fp16 reads, fp32 accumulate, fp16 store)
    gather_kernel<<<(NSEG * 32 + 255) / 256, 256>>>();

    // Fused tensor-core GEMM + epilogue
    cudaFuncSetAttribute(gemm_mma, cudaFuncAttributeMaxDynamicSharedMemorySize,
                         SMEM_TOTAL);
    gemm_mma<<<(NN + 127) / 128, 256, SMEM_TOTAL>>>(conv_bias, node_bias, out);
}

// round 8
// speedup vs baseline: 3.2159x; 1.0719x over previous
#include <cuda_runtime.h>
#include <cuda_fp16.h>
#include <math.h>
#include <stdint.h>

#define NN 100000   // nodes
#define NR 4        // relations
#define NE 250000   // edges per relation
#define DD 128      // feature dim
#define NSEG (NR * NN)                 // 400000 segments
#define NBLK ((NSEG + 1023) / 1024)    // 391 scan blocks

// ---------------------------------------------------------------------------
// Scratch (__device__ globals; allocation-free rule)
// ---------------------------------------------------------------------------
__device__ __align__(16) __half g_xh[(size_t)NN * DD];         // fp16 x, 25.6MB
__device__ __align__(16) __half g_aggh[(size_t)NR * NN * DD];  // fp16 aggregate
__device__ __align__(16) uint32_t g_wtfh[5 * 8 * 8 * 32 * 4];  // f16 paired-frag W
__device__ int g_cnt[NSEG];
__device__ int g_off[NSEG];
__device__ int g_cur[NSEG];
__device__ int g_ssrc[NR * NE];
__device__ int g_bsum[512];

// m16n8k16 F16 mma.sync (family-common PTX), fp32 accumulate
__device__ __forceinline__ void mma16(float* d, const uint32_t* a,
                                      uint32_t b0, uint32_t b1) {
    asm volatile(
        "mma.sync.aligned.m16n8k16.row.col.f32.f16.f16.f32 "
        "{%0,%1,%2,%3}, {%4,%5,%6,%7}, {%8,%9}, {%0,%1,%2,%3};"
        : "+f"(d[0]), "+f"(d[1]), "+f"(d[2]), "+f"(d[3])
        : "r"(a[0]), "r"(a[1]), "r"(a[2]), "r"(a[3]), "r"(b0), "r"(b1));
}

// cp.async 16B (family-common sm_80+); zfill when sz==0
__device__ __forceinline__ void cp16(uint32_t dst, const void* src, int sz) {
    asm volatile("cp.async.cg.shared.global [%0], [%1], 16, %2;"
                 :: "r"(dst), "l"(src), "r"(sz));
}
#define CP_COMMIT() asm volatile("cp.async.commit_group;" ::: "memory")
#define CP_WAIT(n)  asm volatile("cp.async.wait_group %0;" :: "n"(n) : "memory")

__device__ __forceinline__ uint32_t smem_u32(const void* p) {
    uint32_t a;
    asm("{ .reg .u64 t; cvta.to.shared.u64 t, %1; cvt.u32.u64 %0, t; }" : "=r"(a) : "l"(p));
    return a;
}

// ---------------------------------------------------------------------------
// CSR build
// ---------------------------------------------------------------------------
__global__ void hist_kernel(const int* __restrict__ dst) {
    int e = blockIdx.x * blockDim.x + threadIdx.x;
    if (e >= NR * NE) return;
    atomicAdd(&g_cnt[(e / NE) * NN + dst[e]], 1);
}
__global__ void scan1_kernel() {
    __shared__ int sh[1024];
    int gi = blockIdx.x * 1024 + threadIdx.x;
    int v = (gi < NSEG) ? g_cnt[gi] : 0;
    sh[threadIdx.x] = v;
    __syncthreads();
#pragma unroll
    for (int o = 1; o < 1024; o <<= 1) {
        int t = (threadIdx.x >= o) ? sh[threadIdx.x - o] : 0;
        __syncthreads();
        sh[threadIdx.x] += t;
        __syncthreads();
    }
    if (gi < NSEG) g_off[gi] = sh[threadIdx.x] - v;
    if (threadIdx.x == 1023) g_bsum[blockIdx.x] = sh[1023];
}
__global__ void scan2_kernel() {
    __shared__ int sh[512];
    int v = (threadIdx.x < NBLK) ? g_bsum[threadIdx.x] : 0;
    sh[threadIdx.x] = v;
    __syncthreads();
#pragma unroll
    for (int o = 1; o < 512; o <<= 1) {
        int t = (threadIdx.x >= o) ? sh[threadIdx.x - o] : 0;
        __syncthreads();
        sh[threadIdx.x] += t;
        __syncthreads();
    }
    if (threadIdx.x < NBLK) g_bsum[threadIdx.x] = sh[threadIdx.x] - v;
}
__global__ void scan3_kernel() {
    int gi = blockIdx.x * 1024 + threadIdx.x;
    if (gi < NSEG) {
        int o = g_off[gi] + g_bsum[blockIdx.x];
        g_off[gi] = o;
        g_cur[gi] = o;
    }
}
__global__ void place_kernel(const int* __restrict__ src,
                             const int* __restrict__ dst) {
    int e = blockIdx.x * blockDim.x + threadIdx.x;
    if (e >= NR * NE) return;
    int pos = atomicAdd(&g_cur[(e / NE) * NN + dst[e]], 1);
    g_ssrc[pos] = src[e];
}

// ---------------------------------------------------------------------------
// Prep: x -> fp16 (blocks [0,12500)) and W fragment pack (blocks [12500,12660))
// Paired B-fragment order: uint4 (((s*8+t)*8+q)*32+l):
//   x=b0(j=2q), y=b1(j=2q), z=b0(j=2q+1), w=b1(j=2q+1)
//   n = j*8 + l/4 ; k = t*16 + 2*(l%4) + 8*r
// ---------------------------------------------------------------------------
#define NXH_BLK (NN * DD / 4 / 256)   // 12500
__global__ void prep_kernel(const float* __restrict__ x,
                            const float* __restrict__ weight,
                            const float* __restrict__ loop_weight) {
    if (blockIdx.x < NXH_BLK) {
        int idx = blockIdx.x * 256 + threadIdx.x;
        float4 v = reinterpret_cast<const float4*>(x)[idx];
        union { __half2 h[2]; uint2 u; } p;
        p.h[0] = __floats2half2_rn(v.x, v.y);
        p.h[1] = __floats2half2_rn(v.z, v.w);
        reinterpret_cast<uint2*>(g_xh)[idx] = p.u;
    } else {
        int idx = (blockIdx.x - NXH_BLK) * 256 + threadIdx.x;
        if (idx >= 5 * 8 * 8 * 32 * 4) return;
        int c = idx & 3;
        int l = (idx >> 2) & 31;
        int q = (idx >> 7) & 7;
        int t = (idx >> 10) & 7;
        int s = idx >> 13;
        int j = 2 * q + (c >> 1);
        int r = c & 1;
        int n = j * 8 + (l >> 2);
        int k = t * 16 + 2 * (l & 3) + 8 * r;
        const float* W = (s < 4) ? weight + (size_t)s * DD * DD : loop_weight;
        union { __half2 h; uint32_t u; } p;
        p.h = __floats2half2_rn(W[(size_t)k * DD + n], W[(size_t)(k + 1) * DD + n]);
        g_wtfh[idx] = p.u;
    }
}

// ---------------------------------------------------------------------------
// Gather: one warp per (rel,node); reads fp16 x, fp32 accumulate, fp16 store.
// ---------------------------------------------------------------------------
__global__ void gather_kernel() {
    unsigned wid  = (blockIdx.x * blockDim.x + threadIdx.x) >> 5;
    unsigned lane = threadIdx.x & 31;
    if (wid >= (unsigned)NSEG) return;
    int beg = g_off[wid];
    int end = g_cur[wid];
    const uint2* xh2 = reinterpret_cast<const uint2*>(g_xh);
    float a0 = 0.f, a1 = 0.f, a2 = 0.f, a3 = 0.f;
    float b0 = 0.f, b1 = 0.f, b2 = 0.f, b3 = 0.f;
    int e = beg;
    for (; e + 1 < end; e += 2) {
        int s0 = __ldg(&g_ssrc[e]);
        int s1 = __ldg(&g_ssrc[e + 1]);
        uint2 v0 = xh2[(size_t)s0 * 32 + lane];
        uint2 v1 = xh2[(size_t)s1 * 32 + lane];
        float2 p0 = __half22float2(*reinterpret_cast<__half2*>(&v0.x));
        float2 p1 = __half22float2(*reinterpret_cast<__half2*>(&v0.y));
        float2 q0 = __half22float2(*reinterpret_cast<__half2*>(&v1.x));
        float2 q1 = __half22float2(*reinterpret_cast<__half2*>(&v1.y));
        a0 += p0.x; a1 += p0.y; a2 += p1.x; a3 += p1.y;
        b0 += q0.x; b1 += q0.y; b2 += q1.x; b3 += q1.y;
    }
    if (e < end) {
        int s0 = __ldg(&g_ssrc[e]);
        uint2 v0 = xh2[(size_t)s0 * 32 + lane];
        float2 p0 = __half22float2(*reinterpret_cast<__half2*>(&v0.x));
        float2 p1 = __half22float2(*reinterpret_cast<__half2*>(&v0.y));
        a0 += p0.x; a1 += p0.y; a2 += p1.x; a3 += p1.y;
    }
    float rd = 1.0f / fmaxf((float)(end - beg), 1.0f);
    union { __half2 h[2]; uint2 u; } p;
    p.h[0] = __floats2half2_rn((a0 + b0) * rd, (a1 + b1) * rd);
    p.h[1] = __floats2half2_rn((a2 + b2) * rd, (a3 + b3) * rd);
    reinterpret_cast<uint2*>(g_aggh)[(size_t)wid * 32 + lane] = p.u;
}

// ---------------------------------------------------------------------------
// F16 mma.sync fused 5-way GEMM + epilogue, double-buffered cp.async staging.
// Block 256 = 4 M-warps x 2 N-warps; tile M=128, N=128, K=128/stage.
// ---------------------------------------------------------------------------
#define LDAH 136                                   // padded A row (halves)
#define A_BYTES (128 * LDAH * 2)                   // 34816
#define W_BYTES 32768
#define OFF_BIAS 0
#define OFF_A0   2560
#define OFF_A1   (OFF_A0 + A_BYTES)                // 37376
#define OFF_W0   (OFF_A1 + A_BYTES)                // 72192
#define OFF_W1   (OFF_W0 + W_BYTES)                // 104960
#define SMEM_TOTAL (OFF_W1 + W_BYTES)              // 137728

__global__ __launch_bounds__(256)
void gemm_mma(const float* __restrict__ conv_bias,
              const float* __restrict__ node_bias,
              float* __restrict__ out) {
    extern __shared__ char smem[];
    const uint32_t sb = smem_u32(smem);
    float* sbias = reinterpret_cast<float*>(smem + OFF_BIAS);

    const int tid   = threadIdx.x;
    const int lane  = tid & 31;
    const int warp  = tid >> 5;
    const int mwarp = warp & 3;        // 0..3 (M)
    const int nwarp = warp >> 2;       // 0..1 (N)
    const int mbase = blockIdx.x * 128;
    const int lr    = lane >> 2;       // 0..7
    const int lc    = lane & 3;        // 0..3

    for (int i = tid; i < 512; i += 256) sbias[i] = conv_bias[i];
    for (int i = tid; i < 128; i += 256) sbias[512 + i] = node_bias[i];

    // Per-thread copy coordinates (8 x uint4 for A, 8 x uint4 for W per stage)
    const int arow = tid >> 4;              // base row pair: rows arow, arow+16,... step 16
    const int ac8  = tid & 15;

    // stage copy lambda-equivalents
    auto stage_copy = [&](int s, uint32_t abuf, uint32_t wbuf) {
        const uint4* Ag = (s < 4)
            ? reinterpret_cast<const uint4*>(g_aggh) + (size_t)s * NN * 16
            : reinterpret_cast<const uint4*>(g_xh);
#pragma unroll
        for (int it = 0; it < 8; it++) {
            int row = arow + it * 16;
            int gr = mbase + row;
            cp16(abuf + row * (LDAH * 2) + ac8 * 16,
                 Ag + (size_t)gr * 16 + ac8, gr < NN ? 16 : 0);
        }
        const uint4* Wg = reinterpret_cast<const uint4*>(g_wtfh) + (size_t)s * 2048;
#pragma unroll
        for (int it = 0; it < 8; it++)
            cp16(wbuf + (tid + it * 256) * 16, Wg + tid + it * 256, 16);
        CP_COMMIT();
    };

    float hsum[2][8][4];
#pragma unroll
    for (int mi = 0; mi < 2; mi++)
#pragma unroll
        for (int j = 0; j < 8; j++)
#pragma unroll
            for (int r = 0; r < 4; r++) hsum[mi][j][r] = 0.f;

    float acc[2][8][4];

    // prologue: stage 0 into buffer 0
    stage_copy(0, sb + OFF_A0, sb + OFF_W0);

    for (int s = 0; s < 5; s++) {
        const uint32_t abuf = (s & 1) ? (sb + OFF_A1) : (sb + OFF_A0);
        const char* asmem = smem + ((s & 1) ? OFF_A1 : OFF_A0);
        const uint4* Bw = reinterpret_cast<const uint4*>(
            smem + ((s & 1) ? OFF_W1 : OFF_W0));
        (void)abuf;

        if (s + 1 < 5) {
            stage_copy(s + 1, (s & 1) ? (sb + OFF_A0) : (sb + OFF_A1),
                              (s & 1) ? (sb + OFF_W0) : (sb + OFF_W1));
            CP_WAIT(1);
        } else {
            CP_WAIT(0);
        }
        __syncthreads();

        const __half* As = reinterpret_cast<const __half*>(asmem);

#pragma unroll
        for (int mi = 0; mi < 2; mi++)
#pragma unroll
            for (int j = 0; j < 8; j++)
#pragma unroll
                for (int r = 0; r < 4; r++) acc[mi][j][r] = 0.f;

        // --- mainloop: 8 k-steps of K=16 ---
#pragma unroll
        for (int t = 0; t < 8; t++) {
            int c0 = t * 16 + 2 * lc;
            uint32_t a[2][4];
#pragma unroll
            for (int mi = 0; mi < 2; mi++) {
                int rr = mwarp * 32 + mi * 16 + lr;
                a[mi][0] = *reinterpret_cast<const uint32_t*>(As + rr * LDAH + c0);
                a[mi][1] = *reinterpret_cast<const uint32_t*>(As + (rr + 8) * LDAH + c0);
                a[mi][2] = *reinterpret_cast<const uint32_t*>(As + rr * LDAH + c0 + 8);
                a[mi][3] = *reinterpret_cast<const uint32_t*>(As + (rr + 8) * LDAH + c0 + 8);
            }
            uint4 b[4];
#pragma unroll
            for (int p = 0; p < 4; p++)
                b[p] = Bw[(t * 8 + nwarp * 4 + p) * 32 + lane];
#pragma unroll
            for (int mi = 0; mi < 2; mi++)
#pragma unroll
                for (int p = 0; p < 4; p++) {
                    mma16(acc[mi][2 * p],     a[mi], b[p].x, b[p].y);
                    mma16(acc[mi][2 * p + 1], a[mi], b[p].z, b[p].w);
                }
        }

        if (s < 4) {
            // --- per-relation epilogue: relu(acc + bias) accumulated ---
#pragma unroll
            for (int mi = 0; mi < 2; mi++)
#pragma unroll
                for (int j = 0; j < 8; j++) {
                    int col = nwarp * 64 + j * 8 + lc * 2;
                    float b0 = sbias[s * 128 + col];
                    float b1 = sbias[s * 128 + col + 1];
                    hsum[mi][j][0] += fmaxf(acc[mi][j][0] + b0, 0.f);
                    hsum[mi][j][1] += fmaxf(acc[mi][j][1] + b1, 0.f);
                    hsum[mi][j][2] += fmaxf(acc[mi][j][2] + b0, 0.f);
                    hsum[mi][j][3] += fmaxf(acc[mi][j][3] + b1, 0.f);
                }
        } else {
            // --- final epilogue: mean, SiLU, + self-loop + node bias, ReLU ---
#pragma unroll
            for (int mi = 0; mi < 2; mi++) {
                int row = mbase + mwarp * 32 + mi * 16 + lr;
#pragma unroll
                for (int j = 0; j < 8; j++) {
                    int col = nwarp * 64 + j * 8 + lc * 2;
                    float nb0 = sbias[512 + col];
                    float nb1 = sbias[512 + col + 1];
                    float h, o0, o1;
                    if (row < NN) {
                        h = hsum[mi][j][0] * 0.25f;
                        h = h / (1.f + __expf(-h));
                        o0 = fmaxf(h + acc[mi][j][0] + nb0, 0.f);
                        h = hsum[mi][j][1] * 0.25f;
                        h = h / (1.f + __expf(-h));
                        o1 = fmaxf(h + acc[mi][j][1] + nb1, 0.f);
                        *reinterpret_cast<float2*>(out + (size_t)row * DD + col) =
                            make_float2(o0, o1);
                    }
                    if (row + 8 < NN) {
                        h = hsum[mi][j][2] * 0.25f;
                        h = h / (1.f + __expf(-h));
                        o0 = fmaxf(h + acc[mi][j][2] + nb0, 0.f);
                        h = hsum[mi][j][3] * 0.25f;
                        h = h / (1.f + __expf(-h));
                        o1 = fmaxf(h + acc[mi][j][3] + nb1, 0.f);
                        *reinterpret_cast<float2*>(out + (size_t)(row + 8) * DD + col) =
                            make_float2(o0, o1);
                    }
                }
            }
        }
        __syncthreads();   // all reads of this stage's buffers done before reuse
    }
}

// ---------------------------------------------------------------------------
extern "C" void kernel_launch(void* const* d_in, const int* in_sizes, int n_in,
                              void* d_out, int out_size) {
    const float* x           = (const float*)d_in[0];
    const float* weight      = (const float*)d_in[1];
    const float* conv_bias   = (const float*)d_in[2];
    const float* loop_weight = (const float*)d_in[3];
    const float* node_bias   = (const float*)d_in[4];
    const int*   src         = (const int*)d_in[5];
    const int*   dst         = (const int*)d_in[6];
    float* out = (float*)d_out;

    // zero histogram via captured async memset (g_bsum zeroing unnecessary:
    // scan2 guards reads with tid < NBLK)
    void* cnt_ptr = nullptr;
    cudaGetSymbolAddress(&cnt_ptr, g_cnt);
    cudaMemsetAsync(cnt_ptr, 0, NSEG * sizeof(int));

    // CSR build
    hist_kernel<<<(NR * NE + 255) / 256, 256>>>(dst);
    scan1_kernel<<<NBLK, 1024>>>();
    scan2_kernel<<<1, 512>>>();
    scan3_kernel<<<NBLK, 1024>>>();
    place_kernel<<<(NR * NE + 255) / 256, 256>>>(src, dst);

    // x -> fp16 + weight fragment pack (one launch)
    prep_kernel<<<NXH_BLK + (5 * 8 * 8 * 32 * 4 + 255) / 256, 256>>>(
        x, weight, loop_weight);

    // Gather (fp16 reads, fp32 accumulate, fp16 store)
    gather_kernel<<<(NSEG * 32 + 255) / 256, 256>>>();

    // Fused tensor-core GEMM + epilogue (double-buffered cp.async)
    cudaFuncSetAttribute(gemm_mma, cudaFuncAttributeMaxDynamicSharedMemorySize,
                         SMEM_TOTAL);
    gemm_mma<<<(NN + 127) / 128, 256, SMEM_TOTAL>>>(conv_bias, node_bias, out);
}

// round 9
// speedup vs baseline: 3.4253x; 1.0651x over previous
#include <cuda_runtime.h>
#include <cuda_fp16.h>
#include <math.h>
#include <stdint.h>

#define NN 100000   // nodes
#define NR 4        // relations
#define NE 250000   // edges per relation
#define DD 128      // feature dim
#define NSEG (NR * NN)                 // 400000 segments
#define CAP 32                         // padded-CSR bucket capacity (P(overflow)~4e-20)

// ---------------------------------------------------------------------------
// Scratch (__device__ globals; allocation-free rule)
// ---------------------------------------------------------------------------
__device__ __align__(16) __half g_xh[(size_t)NN * DD];         // fp16 x, 25.6MB
__device__ __align__(16) __half g_aggh[(size_t)NR * NN * DD];  // fp16 aggregate
__device__ __align__(16) uint32_t g_wtfh[5 * 8 * 8 * 32 * 4];  // f16 paired-frag W
__device__ int g_cnt[NSEG];                                    // per-segment degree
__device__ int g_ssrc[(size_t)NSEG * CAP];                     // padded edge buckets

// m16n8k16 F16 mma.sync (family-common PTX), fp32 accumulate
__device__ __forceinline__ void mma16(float* d, const uint32_t* a,
                                      uint32_t b0, uint32_t b1) {
    asm volatile(
        "mma.sync.aligned.m16n8k16.row.col.f32.f16.f16.f32 "
        "{%0,%1,%2,%3}, {%4,%5,%6,%7}, {%8,%9}, {%0,%1,%2,%3};"
        : "+f"(d[0]), "+f"(d[1]), "+f"(d[2]), "+f"(d[3])
        : "r"(a[0]), "r"(a[1]), "r"(a[2]), "r"(a[3]), "r"(b0), "r"(b1));
}

// cp.async 16B (family-common sm_80+); zfill when sz==0
__device__ __forceinline__ void cp16(uint32_t dst, const void* src, int sz) {
    asm volatile("cp.async.cg.shared.global [%0], [%1], 16, %2;"
                 :: "r"(dst), "l"(src), "r"(sz));
}
#define CP_COMMIT() asm volatile("cp.async.commit_group;" ::: "memory")
#define CP_WAIT(n)  asm volatile("cp.async.wait_group %0;" :: "n"(n) : "memory")

__device__ __forceinline__ uint32_t smem_u32(const void* p) {
    uint32_t a;
    asm("{ .reg .u64 t; cvta.to.shared.u64 t, %1; cvt.u32.u64 %0, t; }" : "=r"(a) : "l"(p));
    return a;
}

// ---------------------------------------------------------------------------
// Padded-CSR placement: one atomic per edge, no scan needed.
// ---------------------------------------------------------------------------
__global__ void place_kernel(const int* __restrict__ src,
                             const int* __restrict__ dst) {
    int e = blockIdx.x * blockDim.x + threadIdx.x;
    if (e >= NR * NE) return;
    int seg = (e / NE) * NN + dst[e];
    int pos = atomicAdd(&g_cnt[seg], 1);
    g_ssrc[(size_t)seg * CAP + pos] = src[e];
}

// ---------------------------------------------------------------------------
// Prep: x -> fp16 (blocks [0,NXH_BLK)) and W fragment pack (rest)
// ---------------------------------------------------------------------------
#define NXH_BLK (NN * DD / 4 / 256)   // 12500
__global__ void prep_kernel(const float* __restrict__ x,
                            const float* __restrict__ weight,
                            const float* __restrict__ loop_weight) {
    if (blockIdx.x < NXH_BLK) {
        int idx = blockIdx.x * 256 + threadIdx.x;
        float4 v = reinterpret_cast<const float4*>(x)[idx];
        union { __half2 h[2]; uint2 u; } p;
        p.h[0] = __floats2half2_rn(v.x, v.y);
        p.h[1] = __floats2half2_rn(v.z, v.w);
        reinterpret_cast<uint2*>(g_xh)[idx] = p.u;
    } else {
        int idx = (blockIdx.x - NXH_BLK) * 256 + threadIdx.x;
        if (idx >= 5 * 8 * 8 * 32 * 4) return;
        int c = idx & 3;
        int l = (idx >> 2) & 31;
        int q = (idx >> 7) & 7;
        int t = (idx >> 10) & 7;
        int s = idx >> 13;
        int j = 2 * q + (c >> 1);
        int r = c & 1;
        int n = j * 8 + (l >> 2);
        int k = t * 16 + 2 * (l & 3) + 8 * r;
        const float* W = (s < 4) ? weight + (size_t)s * DD * DD : loop_weight;
        union { __half2 h; uint32_t u; } p;
        p.h = __floats2half2_rn(W[(size_t)k * DD + n], W[(size_t)(k + 1) * DD + n]);
        g_wtfh[idx] = p.u;
    }
}

// ---------------------------------------------------------------------------
// Gather: one warp per (rel,node); reads fp16 x, fp32 accumulate, fp16 store.
// ---------------------------------------------------------------------------
__global__ void gather_kernel() {
    unsigned wid  = (blockIdx.x * blockDim.x + threadIdx.x) >> 5;
    unsigned lane = threadIdx.x & 31;
    if (wid >= (unsigned)NSEG) return;
    const int* bucket = g_ssrc + (size_t)wid * CAP;
    int deg = g_cnt[wid];
    const uint2* xh2 = reinterpret_cast<const uint2*>(g_xh);
    float a0 = 0.f, a1 = 0.f, a2 = 0.f, a3 = 0.f;
    float b0 = 0.f, b1 = 0.f, b2 = 0.f, b3 = 0.f;
    int e = 0;
    for (; e + 1 < deg; e += 2) {
        int s0 = __ldg(&bucket[e]);
        int s1 = __ldg(&bucket[e + 1]);
        uint2 v0 = xh2[(size_t)s0 * 32 + lane];
        uint2 v1 = xh2[(size_t)s1 * 32 + lane];
        float2 p0 = __half22float2(*reinterpret_cast<__half2*>(&v0.x));
        float2 p1 = __half22float2(*reinterpret_cast<__half2*>(&v0.y));
        float2 q0 = __half22float2(*reinterpret_cast<__half2*>(&v1.x));
        float2 q1 = __half22float2(*reinterpret_cast<__half2*>(&v1.y));
        a0 += p0.x; a1 += p0.y; a2 += p1.x; a3 += p1.y;
        b0 += q0.x; b1 += q0.y; b2 += q1.x; b3 += q1.y;
    }
    if (e < deg) {
        int s0 = __ldg(&bucket[e]);
        uint2 v0 = xh2[(size_t)s0 * 32 + lane];
        float2 p0 = __half22float2(*reinterpret_cast<__half2*>(&v0.x));
        float2 p1 = __half22float2(*reinterpret_cast<__half2*>(&v0.y));
        a0 += p0.x; a1 += p0.y; a2 += p1.x; a3 += p1.y;
    }
    float rd = 1.0f / fmaxf((float)deg, 1.0f);
    union { __half2 h[2]; uint2 u; } p;
    p.h[0] = __floats2half2_rn((a0 + b0) * rd, (a1 + b1) * rd);
    p.h[1] = __floats2half2_rn((a2 + b2) * rd, (a3 + b3) * rd);
    reinterpret_cast<uint2*>(g_aggh)[(size_t)wid * 32 + lane] = p.u;
}

// ---------------------------------------------------------------------------
// F16 mma.sync fused 5-way GEMM + epilogue.
// A double-buffered via cp.async, W single-buffered (refilled post-mainloop).
// smem 105KB -> 2 CTAs/SM.
// ---------------------------------------------------------------------------
#define LDAH 136                                   // padded A row (halves)
#define A_BYTES (128 * LDAH * 2)                   // 34816
#define W_BYTES 32768
#define OFF_BIAS 0
#define OFF_A0   2560
#define OFF_A1   (OFF_A0 + A_BYTES)                // 37376
#define OFF_W    (OFF_A1 + A_BYTES)                // 72192
#define SMEM_TOTAL (OFF_W + W_BYTES)               // 104960

__global__ __launch_bounds__(256, 2)
void gemm_mma(const float* __restrict__ conv_bias,
              const float* __restrict__ node_bias,
              float* __restrict__ out) {
    extern __shared__ char smem[];
    const uint32_t sb = smem_u32(smem);
    float* sbias = reinterpret_cast<float*>(smem + OFF_BIAS);
    const uint4* Bw = reinterpret_cast<const uint4*>(smem + OFF_W);

    const int tid   = threadIdx.x;
    const int lane  = tid & 31;
    const int warp  = tid >> 5;
    const int mwarp = warp & 3;        // 0..3 (M)
    const int nwarp = warp >> 2;       // 0..1 (N)
    const int mbase = blockIdx.x * 128;
    const int lr    = lane >> 2;       // 0..7
    const int lc    = lane & 3;        // 0..3

    for (int i = tid; i < 512; i += 256) sbias[i] = conv_bias[i];
    for (int i = tid; i < 128; i += 256) sbias[512 + i] = node_bias[i];

    const int arow = tid >> 4;
    const int ac8  = tid & 15;

    auto copy_A = [&](int s, uint32_t abuf) {
        const uint4* Ag = (s < 4)
            ? reinterpret_cast<const uint4*>(g_aggh) + (size_t)s * NN * 16
            : reinterpret_cast<const uint4*>(g_xh);
#pragma unroll
        for (int it = 0; it < 8; it++) {
            int row = arow + it * 16;
            int gr = mbase + row;
            cp16(abuf + row * (LDAH * 2) + ac8 * 16,
                 Ag + (size_t)gr * 16 + ac8, gr < NN ? 16 : 0);
        }
        CP_COMMIT();
    };
    auto copy_W = [&](int s) {
        const uint4* Wg = reinterpret_cast<const uint4*>(g_wtfh) + (size_t)s * 2048;
#pragma unroll
        for (int it = 0; it < 8; it++)
            cp16(sb + OFF_W + (tid + it * 256) * 16, Wg + tid + it * 256, 16);
        CP_COMMIT();
    };

    float hsum[2][8][4];
#pragma unroll
    for (int mi = 0; mi < 2; mi++)
#pragma unroll
        for (int j = 0; j < 8; j++)
#pragma unroll
            for (int r = 0; r < 4; r++) hsum[mi][j][r] = 0.f;

    float acc[2][8][4];

    // prologue: A(0) + W(0)
    copy_A(0, sb + OFF_A0);
    copy_W(0);

    for (int s = 0; s < 5; s++) {
        const char* asmem = smem + ((s & 1) ? OFF_A1 : OFF_A0);

        if (s + 1 < 5) {
            copy_A(s + 1, (s & 1) ? (sb + OFF_A0) : (sb + OFF_A1));
            CP_WAIT(1);     // A(s) + W(s) complete; A(s+1) may fly
        } else {
            CP_WAIT(0);
        }
        __syncthreads();

        const __half* As = reinterpret_cast<const __half*>(asmem);

#pragma unroll
        for (int mi = 0; mi < 2; mi++)
#pragma unroll
            for (int j = 0; j < 8; j++)
#pragma unroll
                for (int r = 0; r < 4; r++) acc[mi][j][r] = 0.f;

        // --- mainloop: 8 k-steps of K=16 ---
#pragma unroll
        for (int t = 0; t < 8; t++) {
            int c0 = t * 16 + 2 * lc;
            uint32_t a[2][4];
#pragma unroll
            for (int mi = 0; mi < 2; mi++) {
                int rr = mwarp * 32 + mi * 16 + lr;
                a[mi][0] = *reinterpret_cast<const uint32_t*>(As + rr * LDAH + c0);
                a[mi][1] = *reinterpret_cast<const uint32_t*>(As + (rr + 8) * LDAH + c0);
                a[mi][2] = *reinterpret_cast<const uint32_t*>(As + rr * LDAH + c0 + 8);
                a[mi][3] = *reinterpret_cast<const uint32_t*>(As + (rr + 8) * LDAH + c0 + 8);
            }
            uint4 b[4];
#pragma unroll
            for (int p = 0; p < 4; p++)
                b[p] = Bw[(t * 8 + nwarp * 4 + p) * 32 + lane];
#pragma unroll
            for (int mi = 0; mi < 2; mi++)
#pragma unroll
                for (int p = 0; p < 4; p++) {
                    mma16(acc[mi][2 * p],     a[mi], b[p].x, b[p].y);
                    mma16(acc[mi][2 * p + 1], a[mi], b[p].z, b[p].w);
                }
        }

        if (s < 4) {
            // --- per-relation epilogue: relu(acc + bias) accumulated ---
#pragma unroll
            for (int mi = 0; mi < 2; mi++)
#pragma unroll
                for (int j = 0; j < 8; j++) {
                    int col = nwarp * 64 + j * 8 + lc * 2;
                    float b0 = sbias[s * 128 + col];
                    float b1 = sbias[s * 128 + col + 1];
                    hsum[mi][j][0] += fmaxf(acc[mi][j][0] + b0, 0.f);
                    hsum[mi][j][1] += fmaxf(acc[mi][j][1] + b1, 0.f);
                    hsum[mi][j][2] += fmaxf(acc[mi][j][2] + b0, 0.f);
                    hsum[mi][j][3] += fmaxf(acc[mi][j][3] + b1, 0.f);
                }
            __syncthreads();            // all warps done reading W(s)
            copy_W(s + 1);              // refill W buffer for next stage
        } else {
            // --- final epilogue: mean, SiLU, + self-loop + node bias, ReLU ---
#pragma unroll
            for (int mi = 0; mi < 2; mi++) {
                int row = mbase + mwarp * 32 + mi * 16 + lr;
#pragma unroll
                for (int j = 0; j < 8; j++) {
                    int col = nwarp * 64 + j * 8 + lc * 2;
                    float nb0 = sbias[512 + col];
                    float nb1 = sbias[512 + col + 1];
                    float h, o0, o1;
                    if (row < NN) {
                        h = hsum[mi][j][0] * 0.25f;
                        h = h / (1.f + __expf(-h));
                        o0 = fmaxf(h + acc[mi][j][0] + nb0, 0.f);
                        h = hsum[mi][j][1] * 0.25f;
                        h = h / (1.f + __expf(-h));
                        o1 = fmaxf(h + acc[mi][j][1] + nb1, 0.f);
                        *reinterpret_cast<float2*>(out + (size_t)row * DD + col) =
                            make_float2(o0, o1);
                    }
                    if (row + 8 < NN) {
                        h = hsum[mi][j][2] * 0.25f;
                        h = h / (1.f + __expf(-h));
                        o0 = fmaxf(h + acc[mi][j][2] + nb0, 0.f);
                        h = hsum[mi][j][3] * 0.25f;
                        h = h / (1.f + __expf(-h));
                        o1 = fmaxf(h + acc[mi][j][3] + nb1, 0.f);
                        *reinterpret_cast<float2*>(out + (size_t)(row + 8) * DD + col) =
                            make_float2(o0, o1);
                    }
                }
            }
        }
    }
}

// ---------------------------------------------------------------------------
extern "C" void kernel_launch(void* const* d_in, const int* in_sizes, int n_in,
                              void* d_out, int out_size) {
    const float* x           = (const float*)d_in[0];
    const float* weight      = (const float*)d_in[1];
    const float* conv_bias   = (const float*)d_in[2];
    const float* loop_weight = (const float*)d_in[3];
    const float* node_bias   = (const float*)d_in[4];
    const int*   src         = (const int*)d_in[5];
    const int*   dst         = (const int*)d_in[6];
    float* out = (float*)d_out;

    // zero per-segment degree counters
    void* cnt_ptr = nullptr;
    cudaGetSymbolAddress(&cnt_ptr, g_cnt);
    cudaMemsetAsync(cnt_ptr, 0, NSEG * sizeof(int));

    // padded-CSR placement (replaces hist+scan1+scan2+scan3+place)
    place_kernel<<<(NR * NE + 255) / 256, 256>>>(src, dst);

    // x -> fp16 + weight fragment pack (one launch)
    prep_kernel<<<NXH_BLK + (5 * 8 * 8 * 32 * 4 + 255) / 256, 256>>>(
        x, weight, loop_weight);

    // Gather (fp16 reads, fp32 accumulate, fp16 store)
    gather_kernel<<<(NSEG * 32 + 255) / 256, 256>>>();

    // Fused tensor-core GEMM + epilogue (A double-buffered, 2 CTAs/SM)
    cudaFuncSetAttribute(gemm_mma, cudaFuncAttributeMaxDynamicSharedMemorySize,
                         SMEM_TOTAL);
    gemm_mma<<<(NN + 127) / 128, 256, SMEM_TOTAL>>>(conv_bias, node_bias, out);
}

// round 10
// speedup vs baseline: 3.9541x; 1.1544x over previous
#include <cuda_runtime.h>
#include <cuda_fp16.h>
#include <math.h>
#include <stdint.h>

#define NN 100000   // nodes
#define NR 4        // relations
#define NE 250000   // edges per relation
#define DD 128      // feature dim
#define NSEG (NR * NN)                 // 400000 segments
#define CAP 32                         // padded-CSR bucket capacity (P(overflow)~4e-20)

// ---------------------------------------------------------------------------
// Scratch (__device__ globals; allocation-free rule)
// ---------------------------------------------------------------------------
__device__ __align__(16) __half g_xh[(size_t)NN * DD];         // fp16 x, 25.6MB
__device__ __align__(16) __half g_aggh[(size_t)NR * NN * DD];  // fp16 aggregate
__device__ __align__(16) uint32_t g_wtfh[5 * 8 * 8 * 32 * 4];  // f16 paired-frag W
__device__ int g_cnt[NSEG];                                    // per-segment degree
__device__ int g_ssrc[(size_t)NSEG * CAP];                     // padded edge buckets

// m16n8k16 F16 mma.sync (family-common PTX), fp32 accumulate
__device__ __forceinline__ void mma16(float* d, const uint32_t* a,
                                      uint32_t b0, uint32_t b1) {
    asm volatile(
        "mma.sync.aligned.m16n8k16.row.col.f32.f16.f16.f32 "
        "{%0,%1,%2,%3}, {%4,%5,%6,%7}, {%8,%9}, {%0,%1,%2,%3};"
        : "+f"(d[0]), "+f"(d[1]), "+f"(d[2]), "+f"(d[3])
        : "r"(a[0]), "r"(a[1]), "r"(a[2]), "r"(a[3]), "r"(b0), "r"(b1));
}

// ldmatrix x4 (family-common sm_75+): loads full m16k16 A fragment set
__device__ __forceinline__ void ldsm4(uint32_t* r, uint32_t addr) {
    asm volatile("ldmatrix.sync.aligned.m8n8.x4.shared.b16 {%0,%1,%2,%3}, [%4];"
                 : "=r"(r[0]), "=r"(r[1]), "=r"(r[2]), "=r"(r[3]) : "r"(addr));
}

// cp.async 16B (family-common sm_80+); zfill when sz==0
__device__ __forceinline__ void cp16(uint32_t dst, const void* src, int sz) {
    asm volatile("cp.async.cg.shared.global [%0], [%1], 16, %2;"
                 :: "r"(dst), "l"(src), "r"(sz));
}
#define CP_COMMIT() asm volatile("cp.async.commit_group;" ::: "memory")
#define CP_WAIT(n)  asm volatile("cp.async.wait_group %0;" :: "n"(n) : "memory")

__device__ __forceinline__ uint32_t smem_u32(const void* p) {
    uint32_t a;
    asm("{ .reg .u64 t; cvta.to.shared.u64 t, %1; cvt.u32.u64 %0, t; }" : "=r"(a) : "l"(p));
    return a;
}

// ---------------------------------------------------------------------------
// Mega-prep: [0,NPL) padded-CSR place | [NPL,NPL+NXH) x->fp16 | rest W pack
// ---------------------------------------------------------------------------
#define NPL ((NR * NE + 255) / 256)       // 3907
#define NXH (NN * DD / 4 / 256)           // 12500
#define NWT ((5 * 8 * 8 * 32 * 4 + 255) / 256)  // 160
__global__ void prep_kernel(const int* __restrict__ src,
                            const int* __restrict__ dst,
                            const float* __restrict__ x,
                            const float* __restrict__ weight,
                            const float* __restrict__ loop_weight) {
    if (blockIdx.x < NPL) {
        int e = blockIdx.x * 256 + threadIdx.x;
        if (e >= NR * NE) return;
        int seg = (e / NE) * NN + dst[e];
        int pos = atomicAdd(&g_cnt[seg], 1);
        g_ssrc[(size_t)seg * CAP + pos] = src[e];
    } else if (blockIdx.x < NPL + NXH) {
        int idx = (blockIdx.x - NPL) * 256 + threadIdx.x;
        float4 v = reinterpret_cast<const float4*>(x)[idx];
        union { __half2 h[2]; uint2 u; } p;
        p.h[0] = __floats2half2_rn(v.x, v.y);
        p.h[1] = __floats2half2_rn(v.z, v.w);
        reinterpret_cast<uint2*>(g_xh)[idx] = p.u;
    } else {
        int idx = (blockIdx.x - NPL - NXH) * 256 + threadIdx.x;
        if (idx >= 5 * 8 * 8 * 32 * 4) return;
        int c = idx & 3;
        int l = (idx >> 2) & 31;
        int q = (idx >> 7) & 7;
        int t = (idx >> 10) & 7;
        int s = idx >> 13;
        int j = 2 * q + (c >> 1);
        int r = c & 1;
        int n = j * 8 + (l >> 2);
        int k = t * 16 + 2 * (l & 3) + 8 * r;
        const float* W = (s < 4) ? weight + (size_t)s * DD * DD : loop_weight;
        union { __half2 h; uint32_t u; } p;
        p.h = __floats2half2_rn(W[(size_t)k * DD + n], W[(size_t)(k + 1) * DD + n]);
        g_wtfh[idx] = p.u;
    }
}

// ---------------------------------------------------------------------------
// Gather: one warp per (rel,node); reads fp16 x, fp32 accumulate, fp16 store.
// ---------------------------------------------------------------------------
__global__ void gather_kernel() {
    unsigned wid  = (blockIdx.x * blockDim.x + threadIdx.x) >> 5;
    unsigned lane = threadIdx.x & 31;
    if (wid >= (unsigned)NSEG) return;
    const int* bucket = g_ssrc + (size_t)wid * CAP;
    int deg = g_cnt[wid];
    const uint2* xh2 = reinterpret_cast<const uint2*>(g_xh);
    float a0 = 0.f, a1 = 0.f, a2 = 0.f, a3 = 0.f;
    float b0 = 0.f, b1 = 0.f, b2 = 0.f, b3 = 0.f;
    int e = 0;
    for (; e + 1 < deg; e += 2) {
        int s0 = __ldg(&bucket[e]);
        int s1 = __ldg(&bucket[e + 1]);
        uint2 v0 = xh2[(size_t)s0 * 32 + lane];
        uint2 v1 = xh2[(size_t)s1 * 32 + lane];
        float2 p0 = __half22float2(*reinterpret_cast<__half2*>(&v0.x));
        float2 p1 = __half22float2(*reinterpret_cast<__half2*>(&v0.y));
        float2 q0 = __half22float2(*reinterpret_cast<__half2*>(&v1.x));
        float2 q1 = __half22float2(*reinterpret_cast<__half2*>(&v1.y));
        a0 += p0.x; a1 += p0.y; a2 += p1.x; a3 += p1.y;
        b0 += q0.x; b1 += q0.y; b2 += q1.x; b3 += q1.y;
    }
    if (e < deg) {
        int s0 = __ldg(&bucket[e]);
        uint2 v0 = xh2[(size_t)s0 * 32 + lane];
        float2 p0 = __half22float2(*reinterpret_cast<__half2*>(&v0.x));
        float2 p1 = __half22float2(*reinterpret_cast<__half2*>(&v0.y));
        a0 += p0.x; a1 += p0.y; a2 += p1.x; a3 += p1.y;
    }
    float rd = 1.0f / fmaxf((float)deg, 1.0f);
    union { __half2 h[2]; uint2 u; } p;
    p.h[0] = __floats2half2_rn((a0 + b0) * rd, (a1 + b1) * rd);
    p.h[1] = __floats2half2_rn((a2 + b2) * rd, (a3 + b3) * rd);
    reinterpret_cast<uint2*>(g_aggh)[(size_t)wid * 32 + lane] = p.u;
}

// ---------------------------------------------------------------------------
// F16 mma.sync fused 5-way GEMM + epilogue.
// Tile M=64, N=128, K=128/stage. Block 256 = 2 M-warps x 4 N-warps.
// A via ldmatrix.x4, double-buffered cp.async; W single-buffer refill.
// ~95 regs -> no spills under launch_bounds(256,2).
// ---------------------------------------------------------------------------
#define MT 64
#define LDAH 136                                   // padded A row (halves)
#define A_BYTES (MT * LDAH * 2)                    // 17408
#define W_BYTES 32768
#define OFF_BIAS 0
#define OFF_A0   2560
#define OFF_A1   (OFF_A0 + A_BYTES)                // 19968
#define OFF_W    (OFF_A1 + A_BYTES)                // 37376
#define SMEM_TOTAL (OFF_W + W_BYTES)               // 70144

__global__ __launch_bounds__(256, 2)
void gemm_mma(const float* __restrict__ conv_bias,
              const float* __restrict__ node_bias,
              float* __restrict__ out) {
    extern __shared__ char smem[];
    const uint32_t sb = smem_u32(smem);
    float* sbias = reinterpret_cast<float*>(smem + OFF_BIAS);
    const uint4* Bw = reinterpret_cast<const uint4*>(smem + OFF_W);

    const int tid   = threadIdx.x;
    const int lane  = tid & 31;
    const int warp  = tid >> 5;
    const int mwarp = warp & 1;        // 0..1 (M, 32 rows each)
    const int nwarp = warp >> 1;       // 0..3 (N, 32 cols each)
    const int mbase = blockIdx.x * MT;
    const int lr    = lane >> 2;       // 0..7
    const int lc    = lane & 3;        // 0..3

    for (int i = tid; i < 512; i += 256) sbias[i] = conv_bias[i];
    for (int i = tid; i < 128; i += 256) sbias[512 + i] = node_bias[i];

    const int arow = tid >> 4;         // 0..15
    const int ac8  = tid & 15;

    auto copy_A = [&](int s, uint32_t abuf) {
        const uint4* Ag = (s < 4)
            ? reinterpret_cast<const uint4*>(g_aggh) + (size_t)s * NN * 16
            : reinterpret_cast<const uint4*>(g_xh);
#pragma unroll
        for (int it = 0; it < 4; it++) {
            int row = arow + it * 16;
            int gr = mbase + row;
            cp16(abuf + row * (LDAH * 2) + ac8 * 16,
                 Ag + (size_t)gr * 16 + ac8, gr < NN ? 16 : 0);
        }
        CP_COMMIT();
    };
    auto copy_W = [&](int s) {
        const uint4* Wg = reinterpret_cast<const uint4*>(g_wtfh) + (size_t)s * 2048;
#pragma unroll
        for (int it = 0; it < 8; it++)
            cp16(sb + OFF_W + (tid + it * 256) * 16, Wg + tid + it * 256, 16);
        CP_COMMIT();
    };

    float hsum[2][4][4];
#pragma unroll
    for (int mi = 0; mi < 2; mi++)
#pragma unroll
        for (int j = 0; j < 4; j++)
#pragma unroll
            for (int r = 0; r < 4; r++) hsum[mi][j][r] = 0.f;

    float acc[2][4][4];

    // ldmatrix per-lane address pieces (row/col within A tile)
    const int lm_row = lane & 15;            // row offset within m16 tile
    const int lm_col = (lane >> 4) * 16;     // 0 or 16 bytes (k-half)

    copy_A(0, sb + OFF_A0);
    copy_W(0);

    for (int s = 0; s < 5; s++) {
        const uint32_t abase = sb + ((s & 1) ? OFF_A1 : OFF_A0);

        if (s + 1 < 5) {
            copy_A(s + 1, (s & 1) ? (sb + OFF_A0) : (sb + OFF_A1));
            CP_WAIT(1);     // A(s)+W(s) landed; A(s+1) in flight
        } else {
            CP_WAIT(0);
        }
        __syncthreads();

#pragma unroll
        for (int mi = 0; mi < 2; mi++)
#pragma unroll
            for (int j = 0; j < 4; j++)
#pragma unroll
                for (int r = 0; r < 4; r++) acc[mi][j][r] = 0.f;

        // --- mainloop: 8 k-steps of K=16 ---
#pragma unroll
        for (int t = 0; t < 8; t++) {
            uint32_t a[2][4];
#pragma unroll
            for (int mi = 0; mi < 2; mi++) {
                int rr = mwarp * 32 + mi * 16 + lm_row;
                ldsm4(a[mi], abase + rr * (LDAH * 2) + t * 32 + lm_col);
            }
            uint4 b[2];
#pragma unroll
            for (int p = 0; p < 2; p++)
                b[p] = Bw[(t * 8 + nwarp * 2 + p) * 32 + lane];
#pragma unroll
            for (int mi = 0; mi < 2; mi++)
#pragma unroll
                for (int p = 0; p < 2; p++) {
                    mma16(acc[mi][2 * p],     a[mi], b[p].x, b[p].y);
                    mma16(acc[mi][2 * p + 1], a[mi], b[p].z, b[p].w);
                }
        }

        if (s < 4) {
            // --- per-relation epilogue: relu(acc + bias) accumulated ---
#pragma unroll
            for (int mi = 0; mi < 2; mi++)
#pragma unroll
                for (int j = 0; j < 4; j++) {
                    int col = nwarp * 32 + j * 8 + lc * 2;
                    float b0 = sbias[s * 128 + col];
                    float b1 = sbias[s * 128 + col + 1];
                    hsum[mi][j][0] += fmaxf(acc[mi][j][0] + b0, 0.f);
                    hsum[mi][j][1] += fmaxf(acc[mi][j][1] + b1, 0.f);
                    hsum[mi][j][2] += fmaxf(acc[mi][j][2] + b0, 0.f);
                    hsum[mi][j][3] += fmaxf(acc[mi][j][3] + b1, 0.f);
                }
            __syncthreads();            // all warps done reading W(s)
            copy_W(s + 1);              // refill W buffer for next stage
        } else {
            // --- final epilogue: mean, SiLU, + self-loop + node bias, ReLU ---
#pragma unroll
            for (int mi = 0; mi < 2; mi++) {
                int row = mbase + mwarp * 32 + mi * 16 + lr;
#pragma unroll
                for (int j = 0; j < 4; j++) {
                    int col = nwarp * 32 + j * 8 + lc * 2;
                    float nb0 = sbias[512 + col];
                    float nb1 = sbias[512 + col + 1];
                    float h, o0, o1;
                    if (row < NN) {
                        h = hsum[mi][j][0] * 0.25f;
                        h = h / (1.f + __expf(-h));
                        o0 = fmaxf(h + acc[mi][j][0] + nb0, 0.f);
                        h = hsum[mi][j][1] * 0.25f;
                        h = h / (1.f + __expf(-h));
                        o1 = fmaxf(h + acc[mi][j][1] + nb1, 0.f);
                        *reinterpret_cast<float2*>(out + (size_t)row * DD + col) =
                            make_float2(o0, o1);
                    }
                    if (row + 8 < NN) {
                        h = hsum[mi][j][2] * 0.25f;
                        h = h / (1.f + __expf(-h));
                        o0 = fmaxf(h + acc[mi][j][2] + nb0, 0.f);
                        h = hsum[mi][j][3] * 0.25f;
                        h = h / (1.f + __expf(-h));
                        o1 = fmaxf(h + acc[mi][j][3] + nb1, 0.f);
                        *reinterpret_cast<float2*>(out + (size_t)(row + 8) * DD + col) =
                            make_float2(o0, o1);
                    }
                }
            }
        }
    }
}

// ---------------------------------------------------------------------------
extern "C" void kernel_launch(void* const* d_in, const int* in_sizes, int n_in,
                              void* d_out, int out_size) {
    const float* x           = (const float*)d_in[0];
    const float* weight      = (const float*)d_in[1];
    const float* conv_bias   = (const float*)d_in[2];
    const float* loop_weight = (const float*)d_in[3];
    const float* node_bias   = (const float*)d_in[4];
    const int*   src         = (const int*)d_in[5];
    const int*   dst         = (const int*)d_in[6];
    float* out = (float*)d_out;

    // zero per-segment degree counters
    void* cnt_ptr = nullptr;
    cudaGetSymbolAddress(&cnt_ptr, g_cnt);
    cudaMemsetAsync(cnt_ptr, 0, NSEG * sizeof(int));

    // mega-prep: padded-CSR place + x->fp16 + W fragment pack (one launch)
    prep_kernel<<<NPL + NXH + NWT, 256>>>(src, dst, x, weight, loop_weight);

    // Gather (fp16 reads, fp32 accumulate, fp16 store)
    gather_kernel<<<(NSEG * 32 + 255) / 256, 256>>>();

    // Fused tensor-core GEMM + epilogue (M=64 tiles, ldmatrix, 2 CTAs/SM)
    cudaFuncSetAttribute(gemm_mma, cudaFuncAttributeMaxDynamicSharedMemorySize,
                         SMEM_TOTAL);
    gemm_mma<<<(NN + MT - 1) / MT, 256, SMEM_TOTAL>>>(conv_bias, node_bias, out);
}